// round 15
// baseline (speedup 1.0000x reference)
#include <cuda_runtime.h>

// ---------------- problem constants ----------------
#define NENVS 4096
#define SEQL  128
#define LATD  64
#define EMBD  256
#define HIDD  1024
#define G3    3072          // 3 * HIDD
#define H2    512           // HIDD / 2
#define MENV  32            // envs per CTA
#define NCTA  (NENVS / MENV)
#define NTHR  512

#define OUTS_ELEMS (NENVS * SEQL * 2)

// ---------------- shared memory layout (floats) ----------------
#define SM_H   0                         // h       [32][1024]      32768
#define SM_U   (MENV * HIDD)             // union region base
#define SM_X2  SM_U                      // x2      [32][256]        8192
#define SM_X1  (SM_U + MENV * EMBD)      // x1      [32][32]         1024
#define SM_Z   (SM_X1 + MENV * 32)       // z_t     [32][64]         2048
#define SM_O1  SM_U                      // o1      [32][516] (overlays x1/x2/z)
#define O1STR  516                       // padded stride (bank-conflict avoidance)
#define SM_ST  (SM_U + MENV * O1STR)     // state   [32][2]
#define SM_TOT (SM_ST + MENV * 2)
#define SMEM_BYTES (SM_TOT * 4)

typedef unsigned long long ull;

// h_new scratch: can't overwrite smem h while it is still the K-operand
__device__ float g_hnew[NENVS * HIDD];

// k-pair-packed weights: g_Xpk[kp * ncols + c] = (w[2kp][c], w[2kp+1][c])
__device__ __align__(16) ull g_wihpk[(EMBD / 2) * G3];
__device__ __align__(16) ull g_whhpk[(HIDD / 2) * G3];
__device__ __align__(16) ull g_w3pk [(HIDD / 2) * H2];

// ---------------- f32x2 helpers (PTX-only FFMA2 path on sm_103a) ----------------
__device__ __forceinline__ ull pk2(float lo, float hi) {
    ull r; asm("mov.b64 %0, {%1,%2};" : "=l"(r) : "f"(lo), "f"(hi)); return r;
}
__device__ __forceinline__ float2 upk2(ull v) {
    float2 f; asm("mov.b64 {%0,%1}, %2;" : "=f"(f.x), "=f"(f.y) : "l"(v)); return f;
}
#define FMA2(acc, aa, bb) \
    asm("fma.rn.f32x2 %0, %1, %2, %0;" : "+l"(acc) : "l"(aa), "l"(bb))

__device__ __forceinline__ float sigmf(float x) { return 1.0f / (1.0f + expf(-x)); }
__device__ __forceinline__ float gru1(float rr, float zz, float ni, float nh, float hold) {
    float r = sigmf(rr);
    float u = sigmf(zz);
    float n = tanhf(ni + r * nh);
    return (1.0f - u) * n + u * hold;
}

// ---------------- weight pack kernel (runs before main kernel) ----------------
__global__ void pack_weights_kernel(const float* __restrict__ wih,
                                    const float* __restrict__ whh,
                                    const float* __restrict__ w3) {
    const int n1 = (EMBD / 2) * G3;
    const int n2 = (HIDD / 2) * G3;
    const int n3 = (HIDD / 2) * H2;
    for (int i = blockIdx.x * blockDim.x + threadIdx.x; i < n1 + n2 + n3;
         i += gridDim.x * blockDim.x) {
        if (i < n1) {
            int kp = i / G3, c = i - kp * G3;
            g_wihpk[i] = pk2(wih[(2 * kp) * G3 + c], wih[(2 * kp + 1) * G3 + c]);
        } else if (i < n1 + n2) {
            int j = i - n1;
            int kp = j / G3, c = j - kp * G3;
            g_whhpk[j] = pk2(whh[(2 * kp) * G3 + c], whh[(2 * kp + 1) * G3 + c]);
        } else {
            int j = i - n1 - n2;
            int kp = j / H2, c = j - kp * H2;
            g_w3pk[j] = pk2(w3[(2 * kp) * H2 + c], w3[(2 * kp + 1) * H2 + c]);
        }
    }
}

__global__ __launch_bounds__(NTHR, 1)
void gru_decoder_kernel(
    const float* __restrict__ z,   const float* __restrict__ h0,
    const float* __restrict__ w1,  const float* __restrict__ b1,
    const float* __restrict__ w2,  const float* __restrict__ b2,
    const float* __restrict__ bih, const float* __restrict__ bhh,
    const float* __restrict__ b3,
    const float* __restrict__ w4,  const float* __restrict__ b4,
    float* __restrict__ out, int write_h)
{
    extern __shared__ float sm[];
    const int tid  = threadIdx.x;
    const int env0 = blockIdx.x * MENV;

    float* hs  = sm + SM_H;
    float* x2s = sm + SM_X2;
    float* x1s = sm + SM_X1;
    float* zs  = sm + SM_Z;
    float* o1s = sm + SM_O1;
    float* sts = sm + SM_ST;

    // initial hidden state
    {
        const float4* src = (const float4*)(h0 + (size_t)env0 * HIDD);
        float4* dst = (float4*)hs;
        for (int i = tid; i < MENV * HIDD / 4; i += NTHR) dst[i] = src[i];
    }
    if (tid < MENV * 2) sts[tid] = -2.0f;   // initial fake state/action
    __syncthreads();

    // gate-loop tiling: 128 col-threads x 1 col (128-col nb tiles),
    //                   4 env-groups x 8 envs
    const int ct  = tid & 127;
    const int mt  = tid >> 7;
    const int e0l = mt * 8;

    // x2-layer tiling: 256 col-threads, 2 env-halves of 16
    const int xc  = tid & 255;
    const int xe0 = (tid >> 8) * 16;

    for (int t = 0; t < SEQL; ++t) {
        // ---- stage z_t into smem ----
        for (int i = tid; i < MENV * LATD; i += NTHR) {
            int e = i >> 6, d = i & 63;
            zs[i] = z[((size_t)(env0 + e) * SEQL + t) * LATD + d];
        }
        __syncthreads();

        // ---- x1 = relu([state | z_t] @ w1 + b1)  (K=66, N=32) ----
        for (int o = tid; o < MENV * 32; o += NTHR) {
            int e = o >> 5, c = o & 31;
            float acc = b1[c]
                      + sts[e * 2 + 0] * w1[c]
                      + sts[e * 2 + 1] * w1[32 + c];
            #pragma unroll 8
            for (int k = 0; k < LATD; ++k)
                acc = fmaf(zs[e * LATD + k], w1[(2 + k) * 32 + c], acc);
            x1s[e * 32 + c] = fmaxf(acc, 0.0f);
        }
        __syncthreads();

        // ---- x2 = relu(x1 @ w2 + b2)  (one column, 16 envs per thread) ----
        {
            float acc[16];
            #pragma unroll
            for (int e = 0; e < 16; ++e) acc[e] = b2[xc];
            #pragma unroll 4
            for (int k = 0; k < 32; ++k) {
                float b = __ldg(w2 + k * EMBD + xc);
                #pragma unroll
                for (int e = 0; e < 16; ++e)
                    acc[e] = fmaf(x1s[(xe0 + e) * 32 + k], b, acc[e]);
            }
            #pragma unroll
            for (int e = 0; e < 16; ++e)
                x2s[(xe0 + e) * EMBD + xc] = fmaxf(acc[e], 0.0f);
        }
        __syncthreads();

        // ---- fused GRU gates: per 128-col block, even/odd-k partial sums in
        //      the two f32x2 lanes; lanes summed at combine ----
        for (int nb = 0; nb < HIDD; nb += 128) {
            const int c = nb + ct;                 // single col per thread
            ull aR[8], aZ[8], aNi[8], aNh[8];
            {
                ull r0 = pk2(bih[c] + bhh[c], 0.0f);
                ull z0 = pk2(bih[HIDD + c] + bhh[HIDD + c], 0.0f);
                ull i0 = pk2(bih[2 * HIDD + c], 0.0f);
                ull n0 = pk2(bhh[2 * HIDD + c], 0.0f);
                #pragma unroll
                for (int e = 0; e < 8; ++e) {
                    aR[e] = r0; aZ[e] = z0; aNi[e] = i0; aNh[e] = n0;
                }
            }

            // one k-quad (2 k-pairs) of FMAs; cw[0..2]=pair0 RZN, cw[3..5]=pair1
            auto quad3 = [&](const float* act, int stride, int q,
                             const ull* cw, ull* aN) {
                #pragma unroll
                for (int e = 0; e < 8; ++e) {
                    ulonglong2 av = *(const ulonglong2*)(act + (e0l + e) * stride + q * 4);
                    FMA2(aR[e], av.x, cw[0]);
                    FMA2(aZ[e], av.x, cw[1]);
                    FMA2(aN[e], av.x, cw[2]);
                    FMA2(aR[e], av.y, cw[3]);
                    FMA2(aZ[e], av.y, cw[4]);
                    FMA2(aN[e], av.y, cw[5]);
                }
            };

            // software-pipelined packed-weight stream (prefetch depth: 1 quad)
            auto stream3 = [&](const ull* base, int nq,
                               const float* act, int stride, ull* aN) {
                const ull* p = base;
                ull cw[6], nw[6];
                cw[0] = __ldg(p);            cw[1] = __ldg(p + HIDD);
                cw[2] = __ldg(p + 2 * HIDD);
                cw[3] = __ldg(p + G3);       cw[4] = __ldg(p + G3 + HIDD);
                cw[5] = __ldg(p + G3 + 2 * HIDD);
                p += 2 * G3;
                for (int q = 0; q < nq - 1; ++q) {
                    nw[0] = __ldg(p);            nw[1] = __ldg(p + HIDD);
                    nw[2] = __ldg(p + 2 * HIDD);
                    nw[3] = __ldg(p + G3);       nw[4] = __ldg(p + G3 + HIDD);
                    nw[5] = __ldg(p + G3 + 2 * HIDD);
                    p += 2 * G3;
                    quad3(act, stride, q, cw, aN);
                    #pragma unroll
                    for (int j = 0; j < 6; ++j) cw[j] = nw[j];
                }
                quad3(act, stride, nq - 1, cw, aN);
            };

            stream3(g_wihpk + c, EMBD / 4, x2s, EMBD, aNi);   // x2 @ wih
            stream3(g_whhpk + c, HIDD / 4, hs,  HIDD, aNh);   // h  @ whh

            // combine -> h_new (lane-sum then GRU nonlinearity)
            #pragma unroll
            for (int e = 0; e < 8; ++e) {
                float2 R = upk2(aR[e]);
                float2 Z = upk2(aZ[e]);
                float2 I = upk2(aNi[e]);
                float2 N = upk2(aNh[e]);
                float hold = hs[(e0l + e) * HIDD + c];
                g_hnew[(size_t)(env0 + e0l + e) * HIDD + c] =
                    gru1(R.x + R.y, Z.x + Z.y, I.x + I.y, N.x + N.y, hold);
            }
        }
        __syncthreads();

        // ---- h <- h_new ----
        {
            const float4* src = (const float4*)(g_hnew + (size_t)env0 * HIDD);
            float4* dst = (float4*)hs;
            for (int i = tid; i < MENV * HIDD / 4; i += NTHR) dst[i] = src[i];
        }
        __syncthreads();

        // ---- o1 = relu(h @ w3 + b3)  (N=512, K=1024), 2 cols/thread ----
        for (int nb = 0; nb < H2; nb += 256) {
            const int c = nb + ct * 2;
            ull acc0[8], acc1[8];
            {
                ull i0 = pk2(b3[c], 0.0f);
                ull i1 = pk2(b3[c + 1], 0.0f);
                #pragma unroll
                for (int e = 0; e < 8; ++e) { acc0[e] = i0; acc1[e] = i1; }
            }

            auto o1_quad = [&](int q, ulonglong2 cw0, ulonglong2 cw1) {
                #pragma unroll
                for (int e = 0; e < 8; ++e) {
                    ulonglong2 hv = *(const ulonglong2*)(hs + (e0l + e) * HIDD + q * 4);
                    FMA2(acc0[e], hv.x, cw0.x);
                    FMA2(acc1[e], hv.x, cw0.y);
                    FMA2(acc0[e], hv.y, cw1.x);
                    FMA2(acc1[e], hv.y, cw1.y);
                }
            };

            const ulonglong2* p = (const ulonglong2*)(g_w3pk + c);  // H2/2 u2 per kp
            ulonglong2 cw0 = __ldg(p), cw1 = __ldg(p + H2 / 2);
            p += H2;
            int q = 0;
            for (; q < HIDD / 4 - 1; ++q) {
                ulonglong2 n0 = __ldg(p), n1 = __ldg(p + H2 / 2);
                p += H2;
                o1_quad(q, cw0, cw1);
                cw0 = n0; cw1 = n1;
            }
            o1_quad(q, cw0, cw1);

            #pragma unroll
            for (int e = 0; e < 8; ++e) {
                float2 v0 = upk2(acc0[e]);
                float2 v1 = upk2(acc1[e]);
                float2 ov;
                ov.x = fmaxf(v0.x + v0.y, 0.0f);
                ov.y = fmaxf(v1.x + v1.y, 0.0f);
                *(float2*)(o1s + (e0l + e) * O1STR + c) = ov;
            }
        }
        __syncthreads();

        // ---- o = tanh(o1 @ w4 + b4); emit output; update carried state ----
        if (tid < MENV * 2) {
            const int e = tid >> 1, c = tid & 1;
            float acc = b4[c];
            #pragma unroll 8
            for (int k = 0; k < H2; ++k)
                acc = fmaf(o1s[e * O1STR + k], __ldg(w4 + k * 2 + c), acc);
            float o = tanhf(acc);
            out[((size_t)(env0 + e) * SEQL + t) * 2 + c] = o;
            sts[tid] = o;
        }
        __syncthreads();
    }

    // ---- final hidden state ----
    if (write_h) {
        float* hout = out + OUTS_ELEMS;
        const float4* src = (const float4*)hs;
        float4* dst = (float4*)(hout + (size_t)env0 * HIDD);
        for (int i = tid; i < MENV * HIDD / 4; i += NTHR) dst[i] = src[i];
    }
}

extern "C" void kernel_launch(void* const* d_in, const int* in_sizes, int n_in,
                              void* d_out, int out_size) {
    const float* z    = (const float*)d_in[0];
    const float* hxs  = (const float*)d_in[1];
    const float* w1   = (const float*)d_in[2];
    const float* b1   = (const float*)d_in[3];
    const float* w2   = (const float*)d_in[4];
    const float* b2   = (const float*)d_in[5];
    const float* wih  = (const float*)d_in[6];
    const float* bih  = (const float*)d_in[7];
    const float* whh  = (const float*)d_in[8];
    const float* bhh  = (const float*)d_in[9];
    const float* w3   = (const float*)d_in[10];
    const float* b3   = (const float*)d_in[11];
    const float* w4   = (const float*)d_in[12];
    const float* b4   = (const float*)d_in[13];
    float* out = (float*)d_out;

    const int write_h = (out_size >= OUTS_ELEMS + NENVS * HIDD) ? 1 : 0;

    pack_weights_kernel<<<2048, 512>>>(wih, whh, w3);

    cudaFuncSetAttribute(gru_decoder_kernel,
                         cudaFuncAttributeMaxDynamicSharedMemorySize, SMEM_BYTES);

    gru_decoder_kernel<<<NCTA, NTHR, SMEM_BYTES>>>(
        z, hxs, w1, b1, w2, b2, bih, bhh, b3, w4, b4,
        out, write_h);
}

// round 16
// speedup vs baseline: 1.7996x; 1.7996x over previous
#include <cuda_runtime.h>

// ---------------- problem constants ----------------
#define NENVS 4096
#define SEQL  128
#define LATD  64
#define EMBD  256
#define HIDD  1024
#define G3    3072          // 3 * HIDD
#define H2    512           // HIDD / 2
#define MENV  32            // envs per CTA
#define NCTA  (NENVS / MENV)
#define NTHR  512

#define OUTS_ELEMS (NENVS * SEQL * 2)

// transposed activation row stride (floats): 36 keeps 16B alignment and
// spreads banks (gcd(36,32)=4 -> only 4-way on rare strided accesses)
#define HSTR  36

// ---------------- shared memory layout (floats) ----------------
#define SM_HT  0                          // h_t   [1024][36]   36864
#define SM_U   (HIDD * HSTR)              // union region base
#define SM_X2T SM_U                       // x2_t  [256][36]     9216
#define SM_X1  (SM_U + EMBD * HSTR)       // x1    [32][32]      1024
#define SM_Z   (SM_X1 + MENV * 32)        // z_t   [32][64]      2048
#define SM_O1  SM_U                       // o1    [32][516] (overlay)
#define O1STR  516
#define SM_ST  (SM_U + MENV * O1STR)      // state [32][2]
#define SM_TOT (SM_ST + MENV * 2)
#define SMEM_BYTES (SM_TOT * 4)           // ~213.8 KB

typedef unsigned long long ull;

// h_new scratch, transposed per-CTA block: [cta][col][env]
__device__ float g_hnew[NENVS * HIDD];

// ---------------- f32x2 helpers (PTX-only FFMA2 path on sm_103a) ----------------
__device__ __forceinline__ ull pk2(float lo, float hi) {
    ull r; asm("mov.b64 %0, {%1,%2};" : "=l"(r) : "f"(lo), "f"(hi)); return r;
}
__device__ __forceinline__ float2 upk2(ull v) {
    float2 f; asm("mov.b64 {%0,%1}, %2;" : "=f"(f.x), "=f"(f.y) : "l"(v)); return f;
}
#define FMA2(acc, aa, bb) \
    asm("fma.rn.f32x2 %0, %1, %2, %0;" : "+l"(acc) : "l"(aa), "l"(bb))

__device__ __forceinline__ float sigmf(float x) { return 1.0f / (1.0f + expf(-x)); }
__device__ __forceinline__ float gru1(float rr, float zz, float ni, float nh, float hold) {
    float r = sigmf(rr);
    float u = sigmf(zz);
    float n = tanhf(ni + r * nh);
    return (1.0f - u) * n + u * hold;
}

__global__ __launch_bounds__(NTHR, 1)
void gru_decoder_kernel(
    const float* __restrict__ z,   const float* __restrict__ h0,
    const float* __restrict__ w1,  const float* __restrict__ b1,
    const float* __restrict__ w2,  const float* __restrict__ b2,
    const float* __restrict__ wih, const float* __restrict__ bih,
    const float* __restrict__ whh, const float* __restrict__ bhh,
    const float* __restrict__ w3,  const float* __restrict__ b3,
    const float* __restrict__ w4,  const float* __restrict__ b4,
    float* __restrict__ out, int write_h)
{
    extern __shared__ float sm[];
    const int tid  = threadIdx.x;
    const int env0 = blockIdx.x * MENV;

    float* ht  = sm + SM_HT;    // transposed h: ht[k*HSTR + e]
    float* x2t = sm + SM_X2T;   // transposed x2: x2t[k*HSTR + e]
    float* x1s = sm + SM_X1;
    float* zs  = sm + SM_Z;
    float* o1s = sm + SM_O1;
    float* sts = sm + SM_ST;

    float* hnew_blk = g_hnew + (size_t)blockIdx.x * HIDD * MENV;  // [col][env]

    // initial hidden state -> transposed smem
    for (int i = tid; i < MENV * HIDD; i += NTHR) {
        int e = i >> 10, k = i & (HIDD - 1);
        ht[k * HSTR + e] = h0[(size_t)(env0 + e) * HIDD + k];
    }
    if (tid < MENV * 2) sts[tid] = -2.0f;   // initial fake state/action
    __syncthreads();

    // gate/o1 tiling: 128 col-threads, 4 env-groups x 8 envs (4 f32x2 pairs)
    const int ct  = tid & 127;
    const int mt  = tid >> 7;
    const int e0l = mt * 8;

    // x2-layer tiling: 256 col-threads, 2 env-halves of 16
    const int xc  = tid & 255;
    const int xe0 = (tid >> 8) * 16;

    for (int t = 0; t < SEQL; ++t) {
        // ---- stage z_t into smem ----
        for (int i = tid; i < MENV * LATD; i += NTHR) {
            int e = i >> 6, d = i & 63;
            zs[i] = z[((size_t)(env0 + e) * SEQL + t) * LATD + d];
        }
        __syncthreads();

        // ---- x1 = relu([state | z_t] @ w1 + b1)  (K=66, N=32) ----
        for (int o = tid; o < MENV * 32; o += NTHR) {
            int e = o >> 5, c = o & 31;
            float acc = b1[c]
                      + sts[e * 2 + 0] * w1[c]
                      + sts[e * 2 + 1] * w1[32 + c];
            #pragma unroll 8
            for (int k = 0; k < LATD; ++k)
                acc = fmaf(zs[e * LATD + k], w1[(2 + k) * 32 + c], acc);
            x1s[e * 32 + c] = fmaxf(acc, 0.0f);
        }
        __syncthreads();

        // ---- x2 = relu(x1 @ w2 + b2) -> TRANSPOSED x2t[col][env] ----
        {
            float acc[16];
            #pragma unroll
            for (int e = 0; e < 16; ++e) acc[e] = b2[xc];
            #pragma unroll 4
            for (int k = 0; k < 32; ++k) {
                float b = __ldg(w2 + k * EMBD + xc);
                #pragma unroll
                for (int e = 0; e < 16; ++e)
                    acc[e] = fmaf(x1s[(xe0 + e) * 32 + k], b, acc[e]);
            }
            #pragma unroll
            for (int e = 0; e < 16; ++e)
                x2t[xc * HSTR + xe0 + e] = fmaxf(acc[e], 0.0f);
        }
        __syncthreads();

        // ---- fused GRU gates: envs in f32x2 lanes, transposed activations ----
        for (int nb = 0; nb < HIDD; nb += 128) {
            const int c = nb + ct;                  // one output col per thread
            ull aR[4], aZ[4], aNi[4], aNh[4];
            {
                float bR = bih[c] + bhh[c];
                float bZ = bih[HIDD + c] + bhh[HIDD + c];
                float bI = bih[2 * HIDD + c];
                float bN = bhh[2 * HIDD + c];
                ull r0 = pk2(bR, bR), z0 = pk2(bZ, bZ);
                ull i0 = pk2(bI, bI), n0 = pk2(bN, bN);
                #pragma unroll
                for (int p = 0; p < 4; ++p) {
                    aR[p] = r0; aZ[p] = z0; aNi[p] = i0; aNh[p] = n0;
                }
            }

            // one k-quad of FMAs; wq holds 4x{wr,wz,wn}
            auto fma_quad3 = [&](const float* actT, int q,
                                 const float* wq, ull* aN) {
                #pragma unroll
                for (int kk = 0; kk < 4; ++kk) {
                    const float* ap = actT + (q * 4 + kk) * HSTR + e0l;
                    ulonglong2 a0 = *(const ulonglong2*)ap;        // envs 0..3
                    ulonglong2 a1 = *(const ulonglong2*)(ap + 4);  // envs 4..7
                    ull wR = pk2(wq[kk * 3 + 0], wq[kk * 3 + 0]);
                    ull wZ = pk2(wq[kk * 3 + 1], wq[kk * 3 + 1]);
                    ull wN = pk2(wq[kk * 3 + 2], wq[kk * 3 + 2]);
                    FMA2(aR[0], a0.x, wR); FMA2(aR[1], a0.y, wR);
                    FMA2(aR[2], a1.x, wR); FMA2(aR[3], a1.y, wR);
                    FMA2(aZ[0], a0.x, wZ); FMA2(aZ[1], a0.y, wZ);
                    FMA2(aZ[2], a1.x, wZ); FMA2(aZ[3], a1.y, wZ);
                    FMA2(aN[0], a0.x, wN); FMA2(aN[1], a0.y, wN);
                    FMA2(aN[2], a1.x, wN); FMA2(aN[3], a1.y, wN);
                }
            };
            auto load_quad3 = [&](const float* wbase, int q, float* buf) {
                #pragma unroll
                for (int kk = 0; kk < 4; ++kk) {
                    const float* p = wbase + (size_t)(q * 4 + kk) * G3;
                    buf[kk * 3 + 0] = __ldg(p);
                    buf[kk * 3 + 1] = __ldg(p + HIDD);
                    buf[kk * 3 + 2] = __ldg(p + 2 * HIDD);
                }
            };
            // software-pipelined stream, unrolled x2 (no register shifting)
            auto stream3 = [&](const float* wbase, int NQ,
                               const float* actT, ull* aN) {
                float cw[12], nw[12];
                load_quad3(wbase, 0, cw);
                int q = 0;
                for (; q + 2 < NQ; q += 2) {
                    load_quad3(wbase, q + 1, nw);
                    fma_quad3(actT, q, cw, aN);
                    load_quad3(wbase, q + 2, cw);
                    fma_quad3(actT, q + 1, nw, aN);
                }
                load_quad3(wbase, q + 1, nw);
                fma_quad3(actT, q, cw, aN);
                fma_quad3(actT, q + 1, nw, aN);
            };

            stream3(wih + c, EMBD / 4, x2t, aNi);   // x2 @ wih
            stream3(whh + c, HIDD / 4, ht,  aNh);   // h  @ whh

            // combine: lanes are envs -> direct GRU nonlinearity per env
            #pragma unroll
            for (int p = 0; p < 4; ++p) {
                float2 R = upk2(aR[p]);
                float2 Z = upk2(aZ[p]);
                float2 I = upk2(aNi[p]);
                float2 N = upk2(aNh[p]);
                float2 hold = *(const float2*)(ht + c * HSTR + e0l + 2 * p);
                float2 hv;
                hv.x = gru1(R.x, Z.x, I.x, N.x, hold.x);
                hv.y = gru1(R.y, Z.y, I.y, N.y, hold.y);
                *(float2*)(hnew_blk + (size_t)c * MENV + e0l + 2 * p) = hv;
            }
        }
        __syncthreads();

        // ---- h <- h_new (transposed scratch -> transposed smem, linear) ----
        for (int i = tid; i < HIDD * MENV / 4; i += NTHR) {
            int k = i >> 3, j = i & 7;              // 8 float4 per col
            float4 v = *(const float4*)(hnew_blk + (size_t)k * MENV + j * 4);
            *(float4*)(ht + k * HSTR + j * 4) = v;
        }
        __syncthreads();

        // ---- o1 = relu(h @ w3 + b3)  (N=512, K=1024), env-lane scheme ----
        for (int nb = 0; nb < H2; nb += 256) {
            const int c = nb + ct * 2;              // two cols per thread
            ull acc0[4], acc1[4];
            {
                ull i0 = pk2(b3[c], b3[c]);
                ull i1 = pk2(b3[c + 1], b3[c + 1]);
                #pragma unroll
                for (int p = 0; p < 4; ++p) { acc0[p] = i0; acc1[p] = i1; }
            }

            auto o1_quad = [&](int q, const float2* wq) {
                #pragma unroll
                for (int kk = 0; kk < 4; ++kk) {
                    const float* ap = ht + (q * 4 + kk) * HSTR + e0l;
                    ulonglong2 a0 = *(const ulonglong2*)ap;
                    ulonglong2 a1 = *(const ulonglong2*)(ap + 4);
                    ull w0 = pk2(wq[kk].x, wq[kk].x);
                    ull w1 = pk2(wq[kk].y, wq[kk].y);
                    FMA2(acc0[0], a0.x, w0); FMA2(acc0[1], a0.y, w0);
                    FMA2(acc0[2], a1.x, w0); FMA2(acc0[3], a1.y, w0);
                    FMA2(acc1[0], a0.x, w1); FMA2(acc1[1], a0.y, w1);
                    FMA2(acc1[2], a1.x, w1); FMA2(acc1[3], a1.y, w1);
                }
            };
            auto o1_load = [&](int q, float2* buf) {
                #pragma unroll
                for (int kk = 0; kk < 4; ++kk)
                    buf[kk] = __ldg((const float2*)(w3 + (size_t)(q * 4 + kk) * H2 + c));
            };

            float2 cw[4], nw[4];
            o1_load(0, cw);
            int q = 0;
            for (; q + 2 < HIDD / 4; q += 2) {
                o1_load(q + 1, nw);
                o1_quad(q, cw);
                o1_load(q + 2, cw);
                o1_quad(q + 1, nw);
            }
            o1_load(q + 1, nw);
            o1_quad(q, cw);
            o1_quad(q + 1, nw);

            #pragma unroll
            for (int p = 0; p < 4; ++p) {
                float2 v0 = upk2(acc0[p]);
                float2 v1 = upk2(acc1[p]);
                int e = e0l + 2 * p;
                o1s[e * O1STR + c]           = fmaxf(v0.x, 0.0f);
                o1s[(e + 1) * O1STR + c]     = fmaxf(v0.y, 0.0f);
                o1s[e * O1STR + c + 1]       = fmaxf(v1.x, 0.0f);
                o1s[(e + 1) * O1STR + c + 1] = fmaxf(v1.y, 0.0f);
            }
        }
        __syncthreads();

        // ---- o = tanh(o1 @ w4 + b4); emit output; update carried state ----
        if (tid < MENV * 2) {
            const int e = tid >> 1, c = tid & 1;
            float acc = b4[c];
            #pragma unroll 8
            for (int k = 0; k < H2; ++k)
                acc = fmaf(o1s[e * O1STR + k], __ldg(w4 + k * 2 + c), acc);
            float o = tanhf(acc);
            out[((size_t)(env0 + e) * SEQL + t) * 2 + c] = o;
            sts[tid] = o;
        }
        __syncthreads();
    }

    // ---- final hidden state (de-transpose) ----
    if (write_h) {
        float* hout = out + OUTS_ELEMS;
        for (int i = tid; i < MENV * HIDD; i += NTHR) {
            int e = i >> 10, k = i & (HIDD - 1);
            hout[(size_t)(env0 + e) * HIDD + k] = ht[k * HSTR + e];
        }
    }
}

extern "C" void kernel_launch(void* const* d_in, const int* in_sizes, int n_in,
                              void* d_out, int out_size) {
    const float* z    = (const float*)d_in[0];
    const float* hxs  = (const float*)d_in[1];
    const float* w1   = (const float*)d_in[2];
    const float* b1   = (const float*)d_in[3];
    const float* w2   = (const float*)d_in[4];
    const float* b2   = (const float*)d_in[5];
    const float* wih  = (const float*)d_in[6];
    const float* bih  = (const float*)d_in[7];
    const float* whh  = (const float*)d_in[8];
    const float* bhh  = (const float*)d_in[9];
    const float* w3   = (const float*)d_in[10];
    const float* b3   = (const float*)d_in[11];
    const float* w4   = (const float*)d_in[12];
    const float* b4   = (const float*)d_in[13];
    float* out = (float*)d_out;

    const int write_h = (out_size >= OUTS_ELEMS + NENVS * HIDD) ? 1 : 0;

    cudaFuncSetAttribute(gru_decoder_kernel,
                         cudaFuncAttributeMaxDynamicSharedMemorySize, SMEM_BYTES);

    gru_decoder_kernel<<<NCTA, NTHR, SMEM_BYTES>>>(
        z, hxs, w1, b1, w2, b2, wih, bih, whh, bhh, w3, b3, w4, b4,
        out, write_h);
}